// round 16
// baseline (speedup 1.0000x reference)
#include <cuda_runtime.h>
#include <cuda_fp16.h>
#include <cstddef>

// Problem constants
#define BATCH 2
#define SEQ   2048
#define DIM   1024
#define HEADS 16
#define DH    64
#define MROWS (BATCH * SEQ)      // 4096
// scale/sqrt(dh) with log2(e) folded in: 0.125 * 1.4426950408889634
#define QSCALE 0.18033688011112043f
#define ONES_H2 0x3C003C00u      // half2(1.0, 1.0)

// Scratch (device globals: allocation-free rule) — all fp16
__device__ __half g_ZTh[(size_t)MROWS * DIM];   // 8 MB
__device__ __half g_Wh[(size_t)DIM * DIM];      // 2 MB
__device__ __half g_ZTU[(size_t)MROWS * DIM];   // 8 MB
__device__ __half g_SSA[(size_t)MROWS * DIM];   // 8 MB

// pack two fp32 -> f16x2 (lo -> low half, hi -> high half)
__device__ __forceinline__ unsigned packh2(float lo, float hi) {
    unsigned r;
    asm("cvt.rn.f16x2.f32 %0, %1, %2;" : "=r"(r) : "f"(hi), "f"(lo));
    return r;
}

__device__ __forceinline__ unsigned ex2h2(unsigned x) {
    unsigned r;
    asm("ex2.approx.f16x2 %0, %1;" : "=r"(r) : "r"(x));
    return r;
}

__device__ __forceinline__ void mma_f16(float* c, unsigned a0, unsigned a1,
                                        unsigned a2, unsigned a3,
                                        unsigned b0, unsigned b1) {
    asm volatile(
        "mma.sync.aligned.m16n8k16.row.col.f32.f16.f16.f32 "
        "{%0,%1,%2,%3},{%4,%5,%6,%7},{%8,%9},{%0,%1,%2,%3};"
        : "+f"(c[0]), "+f"(c[1]), "+f"(c[2]), "+f"(c[3])
        : "r"(a0), "r"(a1), "r"(a2), "r"(a3), "r"(b0), "r"(b1));
}

__device__ __forceinline__ void ldsm4(unsigned& r0, unsigned& r1,
                                      unsigned& r2, unsigned& r3, unsigned addr) {
    asm volatile("ldmatrix.sync.aligned.m8n8.x4.shared.b16 {%0,%1,%2,%3}, [%4];"
                 : "=r"(r0), "=r"(r1), "=r"(r2), "=r"(r3) : "r"(addr));
}
__device__ __forceinline__ void ldsm4t(unsigned& r0, unsigned& r1,
                                       unsigned& r2, unsigned& r3, unsigned addr) {
    asm volatile("ldmatrix.sync.aligned.m8n8.x4.trans.shared.b16 {%0,%1,%2,%3}, [%4];"
                 : "=r"(r0), "=r"(r1), "=r"(r2), "=r"(r3) : "r"(addr));
}

__device__ __forceinline__ unsigned smem_u32(const void* p) {
    return (unsigned)__cvta_generic_to_shared(p);
}
__device__ __forceinline__ void cp_async16(unsigned dst, const void* src) {
    asm volatile("cp.async.cg.shared.global [%0], [%1], 16;"
                 :: "r"(dst), "l"(src));
}
__device__ __forceinline__ void cp_commit() {
    asm volatile("cp.async.commit_group;");
}

// ---------------------------------------------------------------------------
// Round fp32 -> fp16 (rn) for BOTH inputs in one launch.
// ---------------------------------------------------------------------------
__global__ void __launch_bounds__(256)
round_f16_all(const float* __restrict__ zt, const float* __restrict__ w,
              __half* __restrict__ zth, __half* __restrict__ wh,
              int zt8, int w8)
{
    int i = blockIdx.x * blockDim.x + threadIdx.x;
    const float* src;
    __half* dst;
    int idx;
    if (i < zt8) { src = zt; dst = zth; idx = i; }
    else if (i < zt8 + w8) { src = w; dst = wh; idx = i - zt8; }
    else return;
    float4 a = ((const float4*)src)[2 * idx];
    float4 b = ((const float4*)src)[2 * idx + 1];
    uint4 o;
    o.x = packh2(a.x, a.y);
    o.y = packh2(a.z, a.w);
    o.z = packh2(b.x, b.y);
    o.w = packh2(b.z, b.w);
    ((uint4*)dst)[idx] = o;
}

// ---------------------------------------------------------------------------
// fp16 tensor-core GEMM, cp.async 3-stage, ldmatrix fragments.
// 256 threads (8 warps, 2x4), warp tile 64x32.
// ---------------------------------------------------------------------------
#define BM 128
#define BN 128
#define BK 32
#define GAST 40
#define GBST 136

template <bool BT, bool OUTH>
__global__ void __launch_bounds__(256)
gemm_f16_kernel(const __half* __restrict__ A, const __half* __restrict__ B,
                void* __restrict__ Cv, int M, int N, int K, size_t dup_off)
{
    __shared__ __align__(16) __half As[3][BM * GAST];
    constexpr int BSZ = BT ? (BN * GAST) : (BK * GBST);
    __shared__ __align__(16) __half Bs[3][BSZ];

    const int tid = threadIdx.x;
    const int warp = tid >> 5;
    const int lane = tid & 31;
    const int wm = (warp >> 2) * 64;     // 0 or 64
    const int wn = (warp & 3) * 32;      // 0,32,64,96
    const int g  = lane >> 2;
    const int t4 = lane & 3;
    const int m0 = blockIdx.y * BM;
    const int n0 = blockIdx.x * BN;

    const int ar = tid >> 2;             // 0..63 (+64)
    const int ac = (tid & 3) * 8;
    const int br = tid >> 4;             // !BT rows 0..15 (+16)
    const int bc = (tid & 15) * 8;

    auto ldg_async = [&](int k0, int s) {
#pragma unroll
        for (int i = 0; i < 2; i++) {
            int row = ar + i * 64;
            cp_async16(smem_u32(&As[s][row * GAST + ac]),
                       &A[(size_t)(m0 + row) * K + k0 + ac]);
        }
        if (BT) {
#pragma unroll
            for (int i = 0; i < 2; i++) {
                int row = ar + i * 64;
                cp_async16(smem_u32(&Bs[s][row * GAST + ac]),
                           &B[(size_t)(n0 + row) * K + k0 + ac]);
            }
        } else {
#pragma unroll
            for (int i = 0; i < 2; i++) {
                int row = br + i * 16;
                cp_async16(smem_u32(&Bs[s][row * GBST + bc]),
                           &B[(size_t)(k0 + row) * N + n0 + bc]);
            }
        }
        cp_commit();
    };

    float acc[4][4][4];
#pragma unroll
    for (int i = 0; i < 4; i++)
#pragma unroll
        for (int j = 0; j < 4; j++)
#pragma unroll
            for (int r = 0; r < 4; r++) acc[i][j][r] = 0.f;

    const int a_row = lane & 15;
    const int a_kgrp = (lane >> 4) << 3;
    const int bt_row = (lane & 7) + ((lane >> 4) & 1) * 8;
    const int bt_kgrp = ((lane >> 3) & 1) * 8;
    const int bn_row = (lane & 7) + ((lane >> 3) & 1) * 8;
    const int bn_ngrp = ((lane >> 4) & 1) * 8;

    const int NIT = K / BK;
    ldg_async(0, 0);
    ldg_async(BK, 1);

    for (int it = 0; it < NIT; it++) {
        if (it + 2 < NIT) {
            ldg_async((it + 2) * BK, (it + 2) % 3);
            asm volatile("cp.async.wait_group 2;");
        } else if (it + 1 < NIT) {
            asm volatile("cp.async.wait_group 1;");
        } else {
            asm volatile("cp.async.wait_group 0;");
        }
        __syncthreads();
        const int s = it % 3;
        const unsigned as_base = smem_u32(As[s]);
        const unsigned bs_base = smem_u32(Bs[s]);

#pragma unroll
        for (int ks = 0; ks < 2; ks++) {
            const int kk = ks * 16;
            unsigned af[4][4], bf[4][2];
#pragma unroll
            for (int mi = 0; mi < 4; mi++) {
                unsigned addr = as_base +
                    ((wm + 16 * mi + a_row) * GAST + kk + a_kgrp) * 2u;
                ldsm4(af[mi][0], af[mi][1], af[mi][2], af[mi][3], addr);
            }
#pragma unroll
            for (int njp = 0; njp < 2; njp++) {
                if (BT) {
                    unsigned addr = bs_base +
                        ((wn + 16 * njp + bt_row) * GAST + kk + bt_kgrp) * 2u;
                    ldsm4(bf[2 * njp][0], bf[2 * njp][1],
                          bf[2 * njp + 1][0], bf[2 * njp + 1][1], addr);
                } else {
                    unsigned addr = bs_base +
                        ((kk + bn_row) * GBST + wn + 16 * njp + bn_ngrp) * 2u;
                    ldsm4t(bf[2 * njp][0], bf[2 * njp][1],
                           bf[2 * njp + 1][0], bf[2 * njp + 1][1], addr);
                }
            }
#pragma unroll
            for (int mi = 0; mi < 4; mi++)
#pragma unroll
                for (int ni = 0; ni < 4; ni++)
                    mma_f16(acc[mi][ni], af[mi][0], af[mi][1], af[mi][2],
                            af[mi][3], bf[ni][0], bf[ni][1]);
        }
        __syncthreads();
    }

    // ---- epilogue ----
#pragma unroll
    for (int mi = 0; mi < 4; mi++) {
#pragma unroll
        for (int ni = 0; ni < 4; ni++) {
            const int row = m0 + wm + 16 * mi + g;
            const int col = n0 + wn + 8 * ni + 2 * t4;
            if (OUTH) {
                __half* C = (__half*)Cv;
                *(unsigned*)&C[(size_t)row * N + col] =
                    packh2(acc[mi][ni][0], acc[mi][ni][1]);
                *(unsigned*)&C[(size_t)(row + 8) * N + col] =
                    packh2(acc[mi][ni][2], acc[mi][ni][3]);
            } else {
                float* C = (float*)Cv;
                float2 v0 = make_float2(acc[mi][ni][0], acc[mi][ni][1]);
                float2 v1 = make_float2(acc[mi][ni][2], acc[mi][ni][3]);
                size_t i0 = (size_t)row * N + col;
                size_t i1 = (size_t)(row + 8) * N + col;
                *(float2*)&C[i0] = v0;
                *(float2*)&C[i1] = v1;
                if (dup_off) {
                    *(float2*)&C[i0 + dup_off] = v0;
                    *(float2*)&C[i1 + dup_off] = v1;
                }
            }
        }
    }
}

// ---------------------------------------------------------------------------
// Flash attention: 256 threads, 8 warps, ONE m16 block per warp (128 q rows
// per CTA). fp16 + ldmatrix, ex2.f16x2 softmax on packed S, ones-column MMA
// row sums. 3-stage cp.async key-tile pipeline.
// grid = (SEQ/128, HEADS, BATCH).
// ---------------------------------------------------------------------------
#define AT_Q 128
#define AT_K 64
#define KP 72    // half stride (144 B)
#define NTILES (SEQ / AT_K)

__global__ void __launch_bounds__(256)
flash_mma_kernel(const __half* __restrict__ ZTU, __half* __restrict__ SSA)
{
    __shared__ __align__(16) __half Kbuf[3][AT_K * KP];   // 27.6 KB

    const int b = blockIdx.z;
    const int h = blockIdx.y;
    const int q0 = blockIdx.x * AT_Q;
    const int tid = threadIdx.x;
    const int warp = tid >> 5;          // 0..7, owns rows warp*16..warp*16+15
    const int lane = tid & 31;
    const int g  = lane >> 2;
    const int t4 = lane & 3;

    const __half* base = ZTU + (size_t)b * SEQ * DIM + (size_t)h * DH;

    // ---- stage 128 Q rows scaled by QSCALE (rn fp16) into Kbuf[0..1] ----
#pragma unroll
    for (int i = 0; i < 4; i++) {
        int f = tid + i * 256;          // 0..1023 16B chunks
        int r = f >> 3;                 // 0..127
        int c8 = (f & 7) * 8;
        uint4 v = *(const uint4*)&base[(size_t)(q0 + r) * DIM + c8];
        __half2* hp = (__half2*)&v;
#pragma unroll
        for (int j = 0; j < 4; j++) {
            float2 fv = __half22float2(hp[j]);
            fv.x *= QSCALE; fv.y *= QSCALE;
            hp[j] = __float22half2_rn(fv);
        }
        *(uint4*)&Kbuf[r >> 6][(r & 63) * KP + c8] = v;
    }
    __syncthreads();

    // ---- Q fragments via ldmatrix.x4 (warp's own 16 rows) ----
    unsigned qa[4][4];
    {
        const int wr = warp * 16;               // global row
        const int buf = wr >> 6;
        const int rloc = wr & 63;
        const int a_row = lane & 15;
        const int a_kgrp = (lane >> 4) << 3;
        const unsigned qb = smem_u32(Kbuf[buf]);
#pragma unroll
        for (int ks = 0; ks < 4; ks++) {
            unsigned addr = qb + ((rloc + a_row) * KP + 16 * ks + a_kgrp) * 2u;
            ldsm4(qa[ks][0], qa[ks][1], qa[ks][2], qa[ks][3], addr);
        }
    }
    __syncthreads();   // done reading Q before cp.async overwrites buffers

    // K/V tile prefetch: 64 rows x 8 chunks = 512 chunks / 256 thr = 2 each
    const int pr = tid >> 3;            // row 0..31 (+32)
    const int pc8 = (tid & 7) * 8;
    auto prefetch = [&](int t, int bufi) {
        const __half* src = base + (size_t)(t * AT_K) * DIM;
#pragma unroll
        for (int i = 0; i < 2; i++) {
            int r = pr + i * 32;
            cp_async16(smem_u32(&Kbuf[bufi][r * KP + pc8]),
                       src + (size_t)r * DIM + pc8);
        }
        cp_commit();
    };

    prefetch(0, 0);
    prefetch(1, 1);

    float oacc[8][4];
#pragma unroll
    for (int j = 0; j < 8; j++)
#pragma unroll
        for (int r = 0; r < 4; r++) oacc[j][r] = 0.f;
    float lacc[4];
#pragma unroll
    for (int r = 0; r < 4; r++) lacc[r] = 0.f;

    const int kb_row = (lane & 7) + ((lane >> 4) & 1) * 8;
    const int kb_kgrp = ((lane >> 3) & 1) * 8;
    const int vb_row = (lane & 7) + ((lane >> 3) & 1) * 8;
    const int vb_ngrp = ((lane >> 4) & 1) * 8;

    for (int t = 0; t < NTILES; t++) {
        if (t + 2 < NTILES) {
            prefetch(t + 2, (t + 2) % 3);
            asm volatile("cp.async.wait_group 2;");
        } else if (t + 1 < NTILES) {
            asm volatile("cp.async.wait_group 1;");
        } else {
            asm volatile("cp.async.wait_group 0;");
        }
        __syncthreads();
        const unsigned kt_base = smem_u32(Kbuf[t % 3]);

        // ---- S = Q @ K^T ----
        float sacc[8][4];
#pragma unroll
        for (int n = 0; n < 8; n++)
#pragma unroll
            for (int r = 0; r < 4; r++) sacc[n][r] = 0.f;
#pragma unroll
        for (int njp = 0; njp < 4; njp++) {
#pragma unroll
            for (int ks = 0; ks < 4; ks++) {
                unsigned b0, b1, b2, b3;
                unsigned addr = kt_base +
                    ((16 * njp + kb_row) * KP + 16 * ks + kb_kgrp) * 2u;
                ldsm4(b0, b1, b2, b3, addr);
                mma_f16(sacc[2 * njp],     qa[ks][0], qa[ks][1], qa[ks][2], qa[ks][3], b0, b1);
                mma_f16(sacc[2 * njp + 1], qa[ks][0], qa[ks][1], qa[ks][2], qa[ks][3], b2, b3);
            }
        }

        // ---- P = exp2(S): pack to h2, ex2.f16x2 (output IS PV A-frag) ----
        unsigned spk[8][2];
#pragma unroll
        for (int n = 0; n < 8; n++) {
            spk[n][0] = ex2h2(packh2(sacc[n][0], sacc[n][1]));
            spk[n][1] = ex2h2(packh2(sacc[n][2], sacc[n][3]));
        }

        // ---- O += P @ V; row sums via ones-column MMA ----
#pragma unroll
        for (int ii = 0; ii < 4; ii++) {
            unsigned pa0 = spk[2 * ii][0],     pa1 = spk[2 * ii][1];
            unsigned pa2 = spk[2 * ii + 1][0], pa3 = spk[2 * ii + 1][1];
            mma_f16(lacc, pa0, pa1, pa2, pa3, ONES_H2, ONES_H2);
#pragma unroll
            for (int jj = 0; jj < 4; jj++) {
                unsigned b0, b1, b2, b3;
                unsigned addr = kt_base +
                    ((16 * ii + vb_row) * KP + 16 * jj + vb_ngrp) * 2u;
                ldsm4t(b0, b1, b2, b3, addr);
                mma_f16(oacc[2 * jj],     pa0, pa1, pa2, pa3, b0, b1);
                mma_f16(oacc[2 * jj + 1], pa0, pa1, pa2, pa3, b2, b3);
            }
        }
        __syncthreads();
    }

    // ---- epilogue: l straight from the ones-MMA accumulator ----
    {
        const float inv0 = 1.f / lacc[0];   // row g
        const float inv1 = 1.f / lacc[2];   // row g+8
        const int row0 = q0 + warp * 16 + g;
        __half* out0 = SSA + ((size_t)(b * SEQ + row0) * DIM) + h * DH;
        __half* out1 = out0 + 8 * DIM;
#pragma unroll
        for (int j = 0; j < 8; j++) {
            *(unsigned*)&out0[8 * j + 2 * t4] =
                packh2(oacc[j][0] * inv0, oacc[j][1] * inv0);
            *(unsigned*)&out1[8 * j + 2 * t4] =
                packh2(oacc[j][2] * inv1, oacc[j][3] * inv1);
        }
    }
}

// ---------------------------------------------------------------------------
extern "C" void kernel_launch(void* const* d_in, const int* in_sizes, int n_in,
                              void* d_out, int out_size)
{
    const float* ZT = (const float*)d_in[0];   // (2,2048,1024)
    const float* W  = (const float*)d_in[1];   // (1024,1024)
    float* out = (float*)d_out;

    __half *zth, *wh, *ztu, *ssa;
    cudaGetSymbolAddress((void**)&zth, g_ZTh);
    cudaGetSymbolAddress((void**)&wh,  g_Wh);
    cudaGetSymbolAddress((void**)&ztu, g_ZTU);
    cudaGetSymbolAddress((void**)&ssa, g_SSA);

    const size_t mssa_elems = (size_t)MROWS * DIM;
    const size_t dup_off = ((size_t)out_size >= 2 * mssa_elems) ? mssa_elems : 0;

    // 0) round both inputs to fp16 (rn), one launch
    const int zt8 = (MROWS * DIM) / 8;
    const int w8  = (DIM * DIM) / 8;
    round_f16_all<<<(zt8 + w8 + 255) / 256, 256>>>(ZT, W, zth, wh, zt8, w8);

    dim3 ggrid(DIM / BN, MROWS / BM);   // (8, 32)

    // 1) ZTU = ZTh @ Wh^T  (fp16 in/out, fp32 accumulate)
    gemm_f16_kernel<true, true><<<ggrid, 256>>>(zth, wh, ztu, MROWS, DIM, DIM, 0);

    // 2) per-head flash self-attention on ZTU (Q=K=V)
    dim3 agrid(SEQ / AT_Q, HEADS, BATCH);   // (16,16,2)
    flash_mma_kernel<<<agrid, 256>>>(ztu, ssa);

    // 3) mssa = SSA @ Wh  (fp32 output, duplicated for the tuple)
    gemm_f16_kernel<false, false><<<ggrid, 256>>>(ssa, wh, out, MROWS, DIM, DIM, dup_off);
}